// round 3
// baseline (speedup 1.0000x reference)
#include <cuda_runtime.h>
#include <cstdint>

// Problem shapes (fixed by the dataset problem)
#define B 32
#define F 1024
#define S 2048
#define TOPK 16

// colsum tiling
#define ROWCH 8                 // row chunks
#define ROWS_PER_CHUNK (S / ROWCH)   // 256
#define COLCH 2                 // column chunks (1024 cols each, as 256 float4)
#define THREADS 256

// Scratch (no allocation allowed in kernel_launch)
__device__ float g_partials[ROWCH * B * S];   // 2 MB
__device__ int   g_topk[B * TOPK];

// ---------------------------------------------------------------------------
// Kernel 1: per-(batch, column) partial sums over row chunks.
// w[b, r, c] row-major. Threads read contiguous float4s -> perfect coalescing.
// 4 independent accumulators => 16 outstanding LDG.128 per thread with unroll.
// ---------------------------------------------------------------------------
__global__ void __launch_bounds__(THREADS) colsum_kernel(const float* __restrict__ w) {
    const int b  = blockIdx.y;
    const int cc = blockIdx.x & (COLCH - 1);   // 0..1
    const int rc = blockIdx.x >> 1;            // 0..7

    const int col4 = cc * THREADS + threadIdx.x;       // float4 column index (0..511)
    const int str  = S / 4;                            // float4 stride per row = 512

    const float4* __restrict__ p =
        reinterpret_cast<const float4*>(w + (size_t)b * S * S + (size_t)(rc * ROWS_PER_CHUNK) * S)
        + col4;

    float4 a0 = make_float4(0.f, 0.f, 0.f, 0.f);
    float4 a1 = a0, a2 = a0, a3 = a0;

    #pragma unroll 4
    for (int r = 0; r < ROWS_PER_CHUNK; r += 4) {
        float4 v0 = p[0];
        float4 v1 = p[str];
        float4 v2 = p[2 * str];
        float4 v3 = p[3 * str];
        p += 4 * str;
        a0.x += v0.x; a0.y += v0.y; a0.z += v0.z; a0.w += v0.w;
        a1.x += v1.x; a1.y += v1.y; a1.z += v1.z; a1.w += v1.w;
        a2.x += v2.x; a2.y += v2.y; a2.z += v2.z; a2.w += v2.w;
        a3.x += v3.x; a3.y += v3.y; a3.z += v3.z; a3.w += v3.w;
    }

    float4 s;
    s.x = (a0.x + a1.x) + (a2.x + a3.x);
    s.y = (a0.y + a1.y) + (a2.y + a3.y);
    s.z = (a0.z + a1.z) + (a2.z + a3.z);
    s.w = (a0.w + a1.w) + (a2.w + a3.w);

    float4* __restrict__ out4 =
        reinterpret_cast<float4*>(g_partials + ((size_t)rc * B + b) * S);
    out4[col4] = s;
}

// ---------------------------------------------------------------------------
// Kernel 2: per-batch top-16 by iterative block-wide argmax.
// Key packing gives descending-value order, lowest-index tie-break — matches
// lax.top_k semantics (index order feeds take_along_axis, so it must match).
// ---------------------------------------------------------------------------
__global__ void __launch_bounds__(THREADS) topk_kernel() {
    __shared__ float vals[S];                       // 8 KB
    __shared__ unsigned long long red[THREADS];

    const int b = blockIdx.x;
    const int t = threadIdx.x;

    // Reduce the 8 row-chunk partials into shared memory.
    for (int c = t; c < S; c += THREADS) {
        float s = 0.f;
        #pragma unroll
        for (int rc = 0; rc < ROWCH; rc++)
            s += g_partials[((size_t)rc * B + b) * S + c];
        vals[c] = s;
    }
    __syncthreads();

    for (int it = 0; it < TOPK; it++) {
        unsigned long long best = 0ull;
        #pragma unroll
        for (int c = t; c < S; c += THREADS) {
            float v = vals[c];
            unsigned fb = __float_as_uint(v);
            fb = (fb & 0x80000000u) ? ~fb : (fb | 0x80000000u);   // order-preserving map
            unsigned long long key =
                ((unsigned long long)fb << 32) | (unsigned)(0xFFFFFFFFu - (unsigned)c);
            if (key > best) best = key;
        }
        red[t] = best;
        __syncthreads();
        #pragma unroll
        for (int off = THREADS / 2; off > 0; off >>= 1) {
            if (t < off) {
                if (red[t + off] > red[t]) red[t] = red[t + off];
            }
            __syncthreads();
        }
        if (t == 0) {
            int c = (int)(0xFFFFFFFFu - (unsigned)(red[0] & 0xFFFFFFFFu));
            g_topk[b * TOPK + it] = c;
            vals[c] = -3.402823466e38f;   // remove from pool
        }
        __syncthreads();
    }
}

// ---------------------------------------------------------------------------
// Kernel 3: gather out[b, f, k] = x[b, f, idx[b][k]].
// One thread per output element; writes fully coalesced.
// ---------------------------------------------------------------------------
__global__ void __launch_bounds__(THREADS) gather_kernel(const float* __restrict__ x,
                                                         float* __restrict__ out) {
    const int t = blockIdx.x * THREADS + threadIdx.x;   // < B*F*TOPK = 524288
    const int k = t & (TOPK - 1);
    const int f = (t >> 4) & (F - 1);
    const int b = t >> 14;
    const int idx = g_topk[b * TOPK + k];
    out[t] = __ldg(x + ((size_t)b * F + f) * S + idx);
}

// ---------------------------------------------------------------------------
extern "C" void kernel_launch(void* const* d_in, const int* in_sizes, int n_in,
                              void* d_out, int out_size) {
    const float* x = (const float*)d_in[0];   // [B, F, S]
    const float* w = (const float*)d_in[1];   // [B, S, S]
    float* out = (float*)d_out;               // [B, F, TOPK]

    (void)in_sizes; (void)n_in; (void)out_size;

    dim3 grid1(COLCH * ROWCH, B);             // (16, 32) = 512 blocks
    colsum_kernel<<<grid1, THREADS>>>(w);

    topk_kernel<<<B, THREADS>>>();

    const int total = B * F * TOPK;           // 524288
    gather_kernel<<<total / THREADS, THREADS>>>(x, out);
}

// round 4
// speedup vs baseline: 1.0663x; 1.0663x over previous
#include <cuda_runtime.h>
#include <cstdint>

// Problem shapes (fixed by the dataset problem)
#define B 32
#define F 1024
#define S 2048
#define TOPK 16

// colsum tiling
#define ROWCH 16                     // row chunks (1024 blocks total -> 1.2% SM imbalance)
#define ROWS_PER_CHUNK (S / ROWCH)   // 128
#define COLCH 2                      // column chunks (1024 cols each, as 256 float4)
#define THREADS 256

// Scratch (no allocation allowed in kernel_launch)
__device__ float g_partials[ROWCH * B * S];   // 4 MB
__device__ int   g_topk[B * TOPK];

// ---------------------------------------------------------------------------
// Kernel 1: per-(batch, column) partial sums over row chunks.
// w[b, r, c] row-major. Threads read contiguous float4s -> perfect coalescing.
// 8 rows unrolled per iteration => 32 front-batched LDG.128 per thread.
// __ldcs: streaming (w is 512MB, no reuse -> don't thrash L2).
// ---------------------------------------------------------------------------
__global__ void __launch_bounds__(THREADS, 4) colsum_kernel(const float* __restrict__ w) {
    const int b  = blockIdx.y;
    const int cc = blockIdx.x & (COLCH - 1);   // 0..1
    const int rc = blockIdx.x >> 1;            // 0..15

    const int col4 = cc * THREADS + threadIdx.x;       // float4 column index (0..511)
    const int str  = S / 4;                            // float4 stride per row = 512

    const float4* __restrict__ p =
        reinterpret_cast<const float4*>(w + (size_t)b * S * S + (size_t)(rc * ROWS_PER_CHUNK) * S)
        + col4;

    float4 a0 = make_float4(0.f, 0.f, 0.f, 0.f);
    float4 a1 = a0, a2 = a0, a3 = a0;

    #pragma unroll
    for (int r = 0; r < ROWS_PER_CHUNK; r += 8) {
        float4 v0 = __ldcs(p + 0 * str);
        float4 v1 = __ldcs(p + 1 * str);
        float4 v2 = __ldcs(p + 2 * str);
        float4 v3 = __ldcs(p + 3 * str);
        float4 v4 = __ldcs(p + 4 * str);
        float4 v5 = __ldcs(p + 5 * str);
        float4 v6 = __ldcs(p + 6 * str);
        float4 v7 = __ldcs(p + 7 * str);
        p += 8 * str;
        a0.x += v0.x; a0.y += v0.y; a0.z += v0.z; a0.w += v0.w;
        a1.x += v1.x; a1.y += v1.y; a1.z += v1.z; a1.w += v1.w;
        a2.x += v2.x; a2.y += v2.y; a2.z += v2.z; a2.w += v2.w;
        a3.x += v3.x; a3.y += v3.y; a3.z += v3.z; a3.w += v3.w;
        a0.x += v4.x; a0.y += v4.y; a0.z += v4.z; a0.w += v4.w;
        a1.x += v5.x; a1.y += v5.y; a1.z += v5.z; a1.w += v5.w;
        a2.x += v6.x; a2.y += v6.y; a2.z += v6.z; a2.w += v6.w;
        a3.x += v7.x; a3.y += v7.y; a3.z += v7.z; a3.w += v7.w;
    }

    float4 s;
    s.x = (a0.x + a1.x) + (a2.x + a3.x);
    s.y = (a0.y + a1.y) + (a2.y + a3.y);
    s.z = (a0.z + a1.z) + (a2.z + a3.z);
    s.w = (a0.w + a1.w) + (a2.w + a3.w);

    float4* __restrict__ out4 =
        reinterpret_cast<float4*>(g_partials + ((size_t)rc * B + b) * S);
    out4[col4] = s;
}

// ---------------------------------------------------------------------------
// Kernel 2: fused partials-reduce + per-batch top-16.
// Each thread holds 8 column sums in registers (c = i*256 + t). Per top-k
// iteration: 7 register compares -> warp shfl-max (5 steps) -> thread 0
// reduces 8 warp maxima. Only 2 __syncthreads per iteration.
// Key packing gives descending-value order, lowest-index tie-break — matches
// lax.top_k semantics (index order feeds take_along_axis, so it must match).
// ---------------------------------------------------------------------------
__global__ void __launch_bounds__(THREADS) topk_kernel() {
    __shared__ unsigned long long s_warp[THREADS / 32];
    __shared__ unsigned long long s_best;

    const int b = blockIdx.x;
    const int t = threadIdx.x;
    const int lane = t & 31;
    const int wid  = t >> 5;

    // Reduce the 16 row-chunk partials into registers (coalesced loads).
    float v[8];
    #pragma unroll
    for (int i = 0; i < 8; i++) {
        const int c = i * THREADS + t;
        float s = 0.f;
        #pragma unroll
        for (int rc = 0; rc < ROWCH; rc++)
            s += g_partials[((size_t)rc * B + b) * S + c];
        v[i] = s;
    }

    for (int it = 0; it < TOPK; it++) {
        unsigned long long best = 0ull;
        #pragma unroll
        for (int i = 0; i < 8; i++) {
            unsigned fb = __float_as_uint(v[i]);
            fb = (fb & 0x80000000u) ? ~fb : (fb | 0x80000000u);   // order-preserving map
            unsigned long long key =
                ((unsigned long long)fb << 32) |
                (unsigned)(0xFFFFFFFFu - (unsigned)(i * THREADS + t));
            best = (key > best) ? key : best;
        }
        #pragma unroll
        for (int off = 16; off > 0; off >>= 1) {
            unsigned long long o = __shfl_xor_sync(0xFFFFFFFFu, best, off);
            best = (o > best) ? o : best;
        }
        if (lane == 0) s_warp[wid] = best;
        __syncthreads();
        if (t == 0) {
            unsigned long long m = s_warp[0];
            #pragma unroll
            for (int j = 1; j < THREADS / 32; j++)
                m = (s_warp[j] > m) ? s_warp[j] : m;
            s_best = m;
            g_topk[b * TOPK + it] =
                (int)(0xFFFFFFFFu - (unsigned)(m & 0xFFFFFFFFull));
        }
        __syncthreads();
        const int c = (int)(0xFFFFFFFFu - (unsigned)(s_best & 0xFFFFFFFFull));
        if ((c & (THREADS - 1)) == t)
            v[c >> 8] = -3.402823466e38f;   // remove winner from pool
    }
}

// ---------------------------------------------------------------------------
// Kernel 3: gather out[b, f, k] = x[b, f, idx[b][k]].
// One thread per output element; writes fully coalesced, reads scattered
// (~16 MB of sectors total -> ~3 us, near floor).
// ---------------------------------------------------------------------------
__global__ void __launch_bounds__(THREADS) gather_kernel(const float* __restrict__ x,
                                                         float* __restrict__ out) {
    const int t = blockIdx.x * THREADS + threadIdx.x;   // < B*F*TOPK = 524288
    const int k = t & (TOPK - 1);
    const int f = (t >> 4) & (F - 1);
    const int b = t >> 14;
    const int idx = g_topk[b * TOPK + k];
    out[t] = __ldg(x + ((size_t)b * F + f) * S + idx);
}

// ---------------------------------------------------------------------------
extern "C" void kernel_launch(void* const* d_in, const int* in_sizes, int n_in,
                              void* d_out, int out_size) {
    const float* x = (const float*)d_in[0];   // [B, F, S]
    const float* w = (const float*)d_in[1];   // [B, S, S]
    float* out = (float*)d_out;               // [B, F, TOPK]

    (void)in_sizes; (void)n_in; (void)out_size;

    dim3 grid1(COLCH * ROWCH, B);             // (32, 32) = 1024 blocks
    colsum_kernel<<<grid1, THREADS>>>(w);

    topk_kernel<<<B, THREADS>>>();

    const int total = B * F * TOPK;           // 524288
    gather_kernel<<<total / THREADS, THREADS>>>(x, out);
}

// round 5
// speedup vs baseline: 1.1116x; 1.0425x over previous
#include <cuda_runtime.h>
#include <cstdint>

// Problem shapes (fixed by the dataset problem)
#define B 32
#define F 1024
#define S 2048
#define TOPK 16

// colsum tiling (R2 config: best measured DRAM% and halves partials traffic)
#define ROWCH 8                      // row chunks
#define ROWS_PER_CHUNK (S / ROWCH)   // 256
#define COLCH 2                      // column chunks (1024 cols each, as 256 float4)
#define THREADS 256

// Scratch (no allocation allowed in kernel_launch)
__device__ float g_partials[ROWCH * B * S];   // 2 MB
__device__ float g_sums[B * S];               // 256 KB
__device__ int   g_topk[B * TOPK];

// ---------------------------------------------------------------------------
// Kernel 1: per-(batch, column) partial sums over row chunks.
// w[b, r, c] row-major. Threads read contiguous float4s -> perfect coalescing.
// 4 independent accumulators, 4-row unroll => 16 outstanding LDG.128/thread.
// This config measured 82.0us @ 83.2% DRAM — the achieved HBM ceiling.
// ---------------------------------------------------------------------------
__global__ void __launch_bounds__(THREADS) colsum_kernel(const float* __restrict__ w) {
    const int b  = blockIdx.y;
    const int cc = blockIdx.x & (COLCH - 1);   // 0..1
    const int rc = blockIdx.x >> 1;            // 0..7

    const int col4 = cc * THREADS + threadIdx.x;       // float4 column index (0..511)
    const int str  = S / 4;                            // float4 stride per row = 512

    const float4* __restrict__ p =
        reinterpret_cast<const float4*>(w + (size_t)b * S * S + (size_t)(rc * ROWS_PER_CHUNK) * S)
        + col4;

    float4 a0 = make_float4(0.f, 0.f, 0.f, 0.f);
    float4 a1 = a0, a2 = a0, a3 = a0;

    #pragma unroll 4
    for (int r = 0; r < ROWS_PER_CHUNK; r += 4) {
        float4 v0 = __ldcs(p + 0 * str);
        float4 v1 = __ldcs(p + 1 * str);
        float4 v2 = __ldcs(p + 2 * str);
        float4 v3 = __ldcs(p + 3 * str);
        p += 4 * str;
        a0.x += v0.x; a0.y += v0.y; a0.z += v0.z; a0.w += v0.w;
        a1.x += v1.x; a1.y += v1.y; a1.z += v1.z; a1.w += v1.w;
        a2.x += v2.x; a2.y += v2.y; a2.z += v2.z; a2.w += v2.w;
        a3.x += v3.x; a3.y += v3.y; a3.z += v3.z; a3.w += v3.w;
    }

    float4 s;
    s.x = (a0.x + a1.x) + (a2.x + a3.x);
    s.y = (a0.y + a1.y) + (a2.y + a3.y);
    s.z = (a0.z + a1.z) + (a2.z + a3.z);
    s.w = (a0.w + a1.w) + (a2.w + a3.w);

    // Plain store: 2 MB lands in L2, gets re-read immediately by reduce_kernel.
    float4* __restrict__ out4 =
        reinterpret_cast<float4*>(g_partials + ((size_t)rc * B + b) * S);
    out4[col4] = s;
}

// ---------------------------------------------------------------------------
// Kernel 2: collapse the 8 row-chunk partials -> g_sums[B][S].
// 256 blocks (chip-wide) instead of doing this inside 32 topk blocks.
// Reads are coalesced per rc slice and should be L2-resident.
// ---------------------------------------------------------------------------
__global__ void __launch_bounds__(THREADS) reduce_kernel() {
    const int i = blockIdx.x * THREADS + threadIdx.x;   // < B*S = 65536
    float s0 = 0.f, s1 = 0.f;
    #pragma unroll
    for (int rc = 0; rc < ROWCH; rc += 2) {
        s0 += g_partials[(size_t)rc * (B * S) + i];
        s1 += g_partials[(size_t)(rc + 1) * (B * S) + i];
    }
    g_sums[i] = s0 + s1;
}

// ---------------------------------------------------------------------------
// Kernel 3: per-batch top-16 by iterative argmax over g_sums[b][:] (8 KB).
// Each thread holds 8 column sums in registers (c = i*256 + t). Per iteration:
// 7 register compares -> warp shfl-max (5 steps) -> thread 0 reduces 8 warp
// maxima. Key packing gives descending-value order, lowest-index tie-break —
// matches lax.top_k semantics (index order feeds take_along_axis).
// ---------------------------------------------------------------------------
__global__ void __launch_bounds__(THREADS) topk_kernel() {
    __shared__ unsigned long long s_warp[THREADS / 32];
    __shared__ unsigned long long s_best;

    const int b = blockIdx.x;
    const int t = threadIdx.x;
    const int lane = t & 31;
    const int wid  = t >> 5;

    float v[8];
    #pragma unroll
    for (int i = 0; i < 8; i++)
        v[i] = g_sums[(size_t)b * S + i * THREADS + t];

    for (int it = 0; it < TOPK; it++) {
        unsigned long long best = 0ull;
        #pragma unroll
        for (int i = 0; i < 8; i++) {
            unsigned fb = __float_as_uint(v[i]);
            fb = (fb & 0x80000000u) ? ~fb : (fb | 0x80000000u);   // order-preserving map
            unsigned long long key =
                ((unsigned long long)fb << 32) |
                (unsigned)(0xFFFFFFFFu - (unsigned)(i * THREADS + t));
            best = (key > best) ? key : best;
        }
        #pragma unroll
        for (int off = 16; off > 0; off >>= 1) {
            unsigned long long o = __shfl_xor_sync(0xFFFFFFFFu, best, off);
            best = (o > best) ? o : best;
        }
        if (lane == 0) s_warp[wid] = best;
        __syncthreads();
        if (t == 0) {
            unsigned long long m = s_warp[0];
            #pragma unroll
            for (int j = 1; j < THREADS / 32; j++)
                m = (s_warp[j] > m) ? s_warp[j] : m;
            s_best = m;
            g_topk[b * TOPK + it] =
                (int)(0xFFFFFFFFu - (unsigned)(m & 0xFFFFFFFFull));
        }
        __syncthreads();
        const int c = (int)(0xFFFFFFFFu - (unsigned)(s_best & 0xFFFFFFFFull));
        if ((c & (THREADS - 1)) == t)
            v[c >> 8] = -3.402823466e38f;   // remove winner from pool
    }
}

// ---------------------------------------------------------------------------
// Kernel 4: gather out[b, f, k] = x[b, f, idx[b][k]].
// One thread per output element; writes fully coalesced, reads scattered
// (524288 distinct 32B sectors = 16 MB -> near floor).
// ---------------------------------------------------------------------------
__global__ void __launch_bounds__(THREADS) gather_kernel(const float* __restrict__ x,
                                                         float* __restrict__ out) {
    const int t = blockIdx.x * THREADS + threadIdx.x;   // < B*F*TOPK = 524288
    const int k = t & (TOPK - 1);
    const int f = (t >> 4) & (F - 1);
    const int b = t >> 14;
    const int idx = g_topk[b * TOPK + k];
    out[t] = __ldg(x + ((size_t)b * F + f) * S + idx);
}

// ---------------------------------------------------------------------------
extern "C" void kernel_launch(void* const* d_in, const int* in_sizes, int n_in,
                              void* d_out, int out_size) {
    const float* x = (const float*)d_in[0];   // [B, F, S]
    const float* w = (const float*)d_in[1];   // [B, S, S]
    float* out = (float*)d_out;               // [B, F, TOPK]

    (void)in_sizes; (void)n_in; (void)out_size;

    dim3 grid1(COLCH * ROWCH, B);             // (16, 32) = 512 blocks
    colsum_kernel<<<grid1, THREADS>>>(w);

    reduce_kernel<<<(B * S) / THREADS, THREADS>>>();   // 256 blocks

    topk_kernel<<<B, THREADS>>>();

    const int total = B * F * TOPK;           // 524288
    gather_kernel<<<total / THREADS, THREADS>>>(x, out);
}

// round 6
// speedup vs baseline: 1.1138x; 1.0020x over previous
#include <cuda_runtime.h>
#include <cstdint>

// Problem shapes (fixed by the dataset problem)
#define B 32
#define F 1024
#define S 2048
#define TOPK 16

// colsum tiling (best measured config: 83% DRAM = LTS chip cap, do not touch)
#define ROWCH 8                      // row chunks
#define ROWS_PER_CHUNK (S / ROWCH)   // 256
#define COLCH 2                      // column chunks (1024 cols each, as 256 float4)
#define THREADS 256

// Scratch (no allocation allowed in kernel_launch)
__device__ float g_partials[ROWCH * B * S];   // 2 MB
__device__ float g_sums[B * S];               // 256 KB
__device__ int   g_topk[B * TOPK];

// ---------------------------------------------------------------------------
// Kernel 1: per-(batch, column) partial sums over row chunks.
// Measured 82us @ 6.6TB/s = LTS chip throughput cap. This is the wall.
// ---------------------------------------------------------------------------
__global__ void __launch_bounds__(THREADS) colsum_kernel(const float* __restrict__ w) {
    const int b  = blockIdx.y;
    const int cc = blockIdx.x & (COLCH - 1);   // 0..1
    const int rc = blockIdx.x >> 1;            // 0..7

    const int col4 = cc * THREADS + threadIdx.x;       // float4 column index (0..511)
    const int str  = S / 4;                            // float4 stride per row = 512

    const float4* __restrict__ p =
        reinterpret_cast<const float4*>(w + (size_t)b * S * S + (size_t)(rc * ROWS_PER_CHUNK) * S)
        + col4;

    float4 a0 = make_float4(0.f, 0.f, 0.f, 0.f);
    float4 a1 = a0, a2 = a0, a3 = a0;

    #pragma unroll 4
    for (int r = 0; r < ROWS_PER_CHUNK; r += 4) {
        float4 v0 = __ldcs(p + 0 * str);
        float4 v1 = __ldcs(p + 1 * str);
        float4 v2 = __ldcs(p + 2 * str);
        float4 v3 = __ldcs(p + 3 * str);
        p += 4 * str;
        a0.x += v0.x; a0.y += v0.y; a0.z += v0.z; a0.w += v0.w;
        a1.x += v1.x; a1.y += v1.y; a1.z += v1.z; a1.w += v1.w;
        a2.x += v2.x; a2.y += v2.y; a2.z += v2.z; a2.w += v2.w;
        a3.x += v3.x; a3.y += v3.y; a3.z += v3.z; a3.w += v3.w;
    }

    float4 s;
    s.x = (a0.x + a1.x) + (a2.x + a3.x);
    s.y = (a0.y + a1.y) + (a2.y + a3.y);
    s.z = (a0.z + a1.z) + (a2.z + a3.z);
    s.w = (a0.w + a1.w) + (a2.w + a3.w);

    // Plain store: 2 MB lands in L2, re-read immediately by reduce_kernel.
    float4* __restrict__ out4 =
        reinterpret_cast<float4*>(g_partials + ((size_t)rc * B + b) * S);
    out4[col4] = s;
}

// ---------------------------------------------------------------------------
// Kernel 2: collapse the 8 row-chunk partials -> g_sums[B][S]. 256 blocks,
// L2-resident reads.
// ---------------------------------------------------------------------------
__global__ void __launch_bounds__(THREADS) reduce_kernel() {
    const int i = blockIdx.x * THREADS + threadIdx.x;   // < B*S = 65536
    float s0 = 0.f, s1 = 0.f;
    #pragma unroll
    for (int rc = 0; rc < ROWCH; rc += 2) {
        s0 += g_partials[(size_t)rc * (B * S) + i];
        s1 += g_partials[(size_t)(rc + 1) * (B * S) + i];
    }
    g_sums[i] = s0 + s1;
}

// ---------------------------------------------------------------------------
// Kernel 3: per-batch top-16 by iterative argmax over g_sums[b][:] (8 KB).
// Key packing gives descending-value order, lowest-index tie-break — matches
// lax.top_k semantics (index order feeds take_along_axis).
// ---------------------------------------------------------------------------
__global__ void __launch_bounds__(THREADS) topk_kernel() {
    __shared__ unsigned long long s_warp[THREADS / 32];
    __shared__ unsigned long long s_best;

    const int b = blockIdx.x;
    const int t = threadIdx.x;
    const int lane = t & 31;
    const int wid  = t >> 5;

    float v[8];
    #pragma unroll
    for (int i = 0; i < 8; i++)
        v[i] = g_sums[(size_t)b * S + i * THREADS + t];

    for (int it = 0; it < TOPK; it++) {
        unsigned long long best = 0ull;
        #pragma unroll
        for (int i = 0; i < 8; i++) {
            unsigned fb = __float_as_uint(v[i]);
            fb = (fb & 0x80000000u) ? ~fb : (fb | 0x80000000u);   // order-preserving map
            unsigned long long key =
                ((unsigned long long)fb << 32) |
                (unsigned)(0xFFFFFFFFu - (unsigned)(i * THREADS + t));
            best = (key > best) ? key : best;
        }
        #pragma unroll
        for (int off = 16; off > 0; off >>= 1) {
            unsigned long long o = __shfl_xor_sync(0xFFFFFFFFu, best, off);
            best = (o > best) ? o : best;
        }
        if (lane == 0) s_warp[wid] = best;
        __syncthreads();
        if (t == 0) {
            unsigned long long m = s_warp[0];
            #pragma unroll
            for (int j = 1; j < THREADS / 32; j++)
                m = (s_warp[j] > m) ? s_warp[j] : m;
            s_best = m;
            g_topk[b * TOPK + it] =
                (int)(0xFFFFFFFFu - (unsigned)(m & 0xFFFFFFFFull));
        }
        __syncthreads();
        const int c = (int)(0xFFFFFFFFu - (unsigned)(s_best & 0xFFFFFFFFull));
        if ((c & (THREADS - 1)) == t)
            v[c >> 8] = -3.402823466e38f;   // remove winner from pool
    }
}

// ---------------------------------------------------------------------------
// Kernel 4: gather, one thread per (b, f) row.
// All 16 loads of a thread land inside ONE 8KB row of x -> DRAM row-buffer
// locality + MLP=16 per thread. idx broadcast via shared memory. Stores are
// 4x float4 per thread = 2KB contiguous per warp (perfectly coalesced).
// ---------------------------------------------------------------------------
__global__ void __launch_bounds__(THREADS) gather_kernel(const float* __restrict__ x,
                                                         float* __restrict__ out) {
    __shared__ int s_idx[TOPK];

    const int b = blockIdx.y;
    const int f = blockIdx.x * THREADS + threadIdx.x;   // 0..F-1

    if (threadIdx.x < TOPK)
        s_idx[threadIdx.x] = g_topk[b * TOPK + threadIdx.x];
    __syncthreads();

    const float* __restrict__ row = x + ((size_t)b * F + f) * S;

    float r[TOPK];
    #pragma unroll
    for (int k = 0; k < TOPK; k++)
        r[k] = __ldg(row + s_idx[k]);

    float4* __restrict__ o4 =
        reinterpret_cast<float4*>(out + ((size_t)b * F + f) * TOPK);
    #pragma unroll
    for (int j = 0; j < TOPK / 4; j++)
        o4[j] = make_float4(r[4 * j], r[4 * j + 1], r[4 * j + 2], r[4 * j + 3]);
}

// ---------------------------------------------------------------------------
extern "C" void kernel_launch(void* const* d_in, const int* in_sizes, int n_in,
                              void* d_out, int out_size) {
    const float* x = (const float*)d_in[0];   // [B, F, S]
    const float* w = (const float*)d_in[1];   // [B, S, S]
    float* out = (float*)d_out;               // [B, F, TOPK]

    (void)in_sizes; (void)n_in; (void)out_size;

    dim3 grid1(COLCH * ROWCH, B);             // (16, 32) = 512 blocks
    colsum_kernel<<<grid1, THREADS>>>(w);

    reduce_kernel<<<(B * S) / THREADS, THREADS>>>();   // 256 blocks

    topk_kernel<<<B, THREADS>>>();

    dim3 grid4(F / THREADS, B);               // (4, 32) = 128 blocks
    gather_kernel<<<grid4, THREADS>>>(x, out);
}